// round 8
// baseline (speedup 1.0000x reference)
#include <cuda_runtime.h>
#include <cuda_fp16.h>

// Sinkhorn rank-one factorization: out = (s0+eps)*r_i*c_j inside the
// [nrows, ncols] block. Matvecs run on an fp16 staged copy of (s0+eps)
// (zero-padded within 16B granules past ncols); output from fp32 s0.
// All hot loops use 16B loads (8 halves / granule), 2 rows per block step.

#define BB 64
#define NN 1024
#define MM 1024
#define SPLIT 16
#define PART (2 * SPLIT)          // partial slots (row-parity split)
#define EPSV 1e-4f

__device__ __align__(16) __half g_sh[(size_t)BB * NN * MM];   // 128 MB (bss)
__device__ __align__(16) float  g_r[BB * NN];
__device__ __align__(16) float  g_c[BB * MM];
__device__ __align__(16) float  g_part[(size_t)BB * PART * MM];

// ---------------------------------------------------------------------------
// Fused: stage (s+eps)->fp16 (granule-zero-padded, valid granules only) AND
// iteration-0 column-sum partials (implicit r=1).
// Thread t: row parity rp = t>>7, granule g = t&127 (8 cols). 2 rows / step.
// ---------------------------------------------------------------------------
__global__ __launch_bounds__(256) void stage_colsum0(
        const float* __restrict__ s,
        const int* __restrict__ nrows,
        const int* __restrict__ ncols) {
    int b = blockIdx.y;
    int t = threadIdx.x;
    int rp = t >> 7, g = t & 127;
    int nr = nrows[b], nc = ncols[b];
    int chunk = (nr + SPLIT - 1) / SPLIT;
    int i0 = blockIdx.x * chunk;
    int i1 = min(i0 + chunk, nr);
    int g8 = g * 8;
    bool mA = g8 < nc, mB = g8 + 4 < nc;
    bool e1 = g8 + 1 < nc, e2 = g8 + 2 < nc, e3 = g8 + 3 < nc;
    bool e5 = g8 + 5 < nc, e6 = g8 + 6 < nc, e7 = g8 + 7 < nc;

    float4 accA = make_float4(0.f, 0.f, 0.f, 0.f);
    float4 accB = make_float4(0.f, 0.f, 0.f, 0.f);

    const float4* __restrict__ sp =
        (const float4*)(s + ((size_t)b * NN + i0 + rp) * MM) + 2 * g;
    uint4* __restrict__ hp =
        (uint4*)(g_sh + ((size_t)b * NN + i0 + rp) * MM) + g;

    for (int i = i0 + rp; i < i1; i += 2) {
        float x0 = 0.f, x1 = 0.f, x2 = 0.f, x3 = 0.f;
        float x4 = 0.f, x5 = 0.f, x6 = 0.f, x7 = 0.f;
        if (mA) {
            float4 v = sp[0];
            x0 = v.x + EPSV;
            x1 = e1 ? v.y + EPSV : 0.f;
            x2 = e2 ? v.z + EPSV : 0.f;
            x3 = e3 ? v.w + EPSV : 0.f;
            if (mB) {
                float4 w = sp[1];
                x4 = w.x + EPSV;
                x5 = e5 ? w.y + EPSV : 0.f;
                x6 = e6 ? w.z + EPSV : 0.f;
                x7 = e7 ? w.w + EPSV : 0.f;
            }
            uint4 h;
            *(__half2*)&h.x = __floats2half2_rn(x0, x1);
            *(__half2*)&h.y = __floats2half2_rn(x2, x3);
            *(__half2*)&h.z = __floats2half2_rn(x4, x5);
            *(__half2*)&h.w = __floats2half2_rn(x6, x7);
            *hp = h;
        }
        accA.x += x0; accA.y += x1; accA.z += x2; accA.w += x3;
        accB.x += x4; accB.y += x5; accB.z += x6; accB.w += x7;
        sp += MM / 2;
        hp += MM / 4;
    }
    float4* pp = (float4*)(g_part +
        ((size_t)b * PART + blockIdx.x * 2 + rp) * MM);
    pp[2 * g] = accA;
    pp[2 * g + 1] = accB;
}

// ---------------------------------------------------------------------------
// c[b,j] = 1 / sum_k part[b,k,j]  (j < ncols; else 1.0)
// ---------------------------------------------------------------------------
__global__ __launch_bounds__(256) void reduce_c_kernel(
        const int* __restrict__ ncols) {
    int b = blockIdx.y;
    int j = blockIdx.x * 256 + threadIdx.x;
    float sum = 0.f;
    #pragma unroll
    for (int k = 0; k < PART; k++)
        sum += g_part[((size_t)b * PART + k) * MM + j];
    g_c[b * MM + j] = (j < ncols[b]) ? (1.0f / sum) : 1.0f;
}

// ---------------------------------------------------------------------------
// Column-sum partials on staged fp16 weighted by r. 16B/thread, 2 rows/step.
// ---------------------------------------------------------------------------
__global__ __launch_bounds__(256) void colsum_h(
        const int* __restrict__ nrows,
        const int* __restrict__ ncols) {
    int b = blockIdx.y;
    int t = threadIdx.x;
    int rp = t >> 7, g = t & 127;
    int nr = nrows[b], nc = ncols[b];
    int chunk = (nr + SPLIT - 1) / SPLIT;
    int i0 = blockIdx.x * chunk;
    int i1 = min(i0 + chunk, nr);

    float4 accA = make_float4(0.f, 0.f, 0.f, 0.f);
    float4 accB = make_float4(0.f, 0.f, 0.f, 0.f);

    if (g * 8 < nc) {
        const uint4* __restrict__ hp =
            (const uint4*)(g_sh + ((size_t)b * NN + i0 + rp) * MM) + g;
        const float* __restrict__ rpr = g_r + b * NN;
        #pragma unroll 4
        for (int i = i0 + rp; i < i1; i += 2) {
            uint4 raw = *hp;
            hp += MM / 4;
            float r = rpr[i];
            float2 a0 = __half22float2(*(__half2*)&raw.x);
            float2 a1 = __half22float2(*(__half2*)&raw.y);
            float2 a2 = __half22float2(*(__half2*)&raw.z);
            float2 a3 = __half22float2(*(__half2*)&raw.w);
            accA.x += a0.x * r; accA.y += a0.y * r;
            accA.z += a1.x * r; accA.w += a1.y * r;
            accB.x += a2.x * r; accB.y += a2.y * r;
            accB.z += a3.x * r; accB.w += a3.y * r;
        }
    }
    float4* pp = (float4*)(g_part +
        ((size_t)b * PART + blockIdx.x * 2 + rp) * MM);
    pp[2 * g] = accA;
    pp[2 * g + 1] = accB;
}

// ---------------------------------------------------------------------------
// r[b,i] = 1 / sum_j staged * c.  Warp per valid row, 16B per lane.
// ---------------------------------------------------------------------------
__global__ __launch_bounds__(256) void rowsum_h(
        const int* __restrict__ nrows,
        const int* __restrict__ ncols) {
    int b = blockIdx.y;
    int lane = threadIdx.x & 31, w = threadIdx.x >> 5;
    int i = blockIdx.x * 8 + w;
    if (i >= nrows[b]) return;
    int nc = ncols[b];

    const uint4* __restrict__ hp =
        (const uint4*)(g_sh + ((size_t)b * NN + i) * MM);
    const float4* __restrict__ cp = (const float4*)(g_c + (size_t)b * MM);
    float acc = 0.f;
    int ng8 = (nc + 7) >> 3;
    #pragma unroll 4
    for (int g = lane; g < ng8; g += 32) {
        uint4 raw = hp[g];
        float4 c0 = cp[2 * g], c1 = cp[2 * g + 1];
        float2 a0 = __half22float2(*(__half2*)&raw.x);
        float2 a1 = __half22float2(*(__half2*)&raw.y);
        float2 a2 = __half22float2(*(__half2*)&raw.z);
        float2 a3 = __half22float2(*(__half2*)&raw.w);
        acc += a0.x * c0.x + a0.y * c0.y + a1.x * c0.z + a1.y * c0.w
             + a2.x * c1.x + a2.y * c1.y + a3.x * c1.z + a3.y * c1.w;
    }
    #pragma unroll
    for (int o = 16; o; o >>= 1) acc += __shfl_xor_sync(0xffffffffu, acc, o);
    if (lane == 0) g_r[b * NN + i] = 1.0f / acc;
}

// ---------------------------------------------------------------------------
// Fused iter-9 rowsum + output materialization (fp32 source for accuracy).
// ---------------------------------------------------------------------------
__global__ __launch_bounds__(256) void rowsum_final(
        const float* __restrict__ s,
        const int* __restrict__ nrows,
        const int* __restrict__ ncols,
        float* __restrict__ out) {
    int b = blockIdx.y;
    int lane = threadIdx.x & 31, w = threadIdx.x >> 5;
    int i = blockIdx.x * 8 + w;
    int nr = nrows[b], nc = ncols[b];
    float4* __restrict__ op = (float4*)(out + ((size_t)b * NN + i) * MM);

    if (i >= nr) {
        float4 z = make_float4(0.f, 0.f, 0.f, 0.f);
        #pragma unroll 2
        for (int k = lane; k < MM / 4; k += 32) op[k] = z;
        return;
    }

    const uint4* __restrict__ hp =
        (const uint4*)(g_sh + ((size_t)b * NN + i) * MM);
    const float4* __restrict__ cp = (const float4*)(g_c + (size_t)b * MM);
    float acc = 0.f;
    int ng8 = (nc + 7) >> 3;
    #pragma unroll 4
    for (int g = lane; g < ng8; g += 32) {
        uint4 raw = hp[g];
        float4 c0 = cp[2 * g], c1 = cp[2 * g + 1];
        float2 a0 = __half22float2(*(__half2*)&raw.x);
        float2 a1 = __half22float2(*(__half2*)&raw.y);
        float2 a2 = __half22float2(*(__half2*)&raw.z);
        float2 a3 = __half22float2(*(__half2*)&raw.w);
        acc += a0.x * c0.x + a0.y * c0.y + a1.x * c0.z + a1.y * c0.w
             + a2.x * c1.x + a2.y * c1.y + a3.x * c1.z + a3.y * c1.w;
    }
    #pragma unroll
    for (int o = 16; o; o >>= 1) acc += __shfl_xor_sync(0xffffffffu, acc, o);
    float r = 1.0f / acc;

    const float4* __restrict__ sp =
        (const float4*)(s + ((size_t)b * NN + i) * MM);
    #pragma unroll 4
    for (int g = lane; g < 128; g += 32) {
        int j = g * 8;
        float4 o0 = make_float4(0.f, 0.f, 0.f, 0.f);
        float4 o1 = make_float4(0.f, 0.f, 0.f, 0.f);
        if (j < nc) {
            float4 v = sp[2 * g];
            float4 c = cp[2 * g];
            o0.x = (v.x + EPSV) * r * c.x;
            if (j + 1 < nc) o0.y = (v.y + EPSV) * r * c.y;
            if (j + 2 < nc) o0.z = (v.z + EPSV) * r * c.z;
            if (j + 3 < nc) o0.w = (v.w + EPSV) * r * c.w;
            if (j + 4 < nc) {
                float4 v2 = sp[2 * g + 1];
                float4 c2 = cp[2 * g + 1];
                o1.x = (v2.x + EPSV) * r * c2.x;
                if (j + 5 < nc) o1.y = (v2.y + EPSV) * r * c2.y;
                if (j + 6 < nc) o1.z = (v2.z + EPSV) * r * c2.z;
                if (j + 7 < nc) o1.w = (v2.w + EPSV) * r * c2.w;
            }
        }
        op[2 * g] = o0;
        op[2 * g + 1] = o1;
    }
}

// ---------------------------------------------------------------------------
extern "C" void kernel_launch(void* const* d_in, const int* in_sizes, int n_in,
                              void* d_out, int out_size) {
    const float* s     = (const float*)d_in[0];
    const int*   nrows = (const int*)d_in[1];
    const int*   ncols = (const int*)d_in[2];
    float*       out   = (float*)d_out;

    dim3 csGrid(SPLIT, BB),    blk(256);
    dim3 rcGrid(MM / 256, BB);
    dim3 rsGrid(NN / 8, BB);

    // iter 0 (col): fused stage + colsum with implicit r = 1
    stage_colsum0<<<csGrid, blk>>>(s, nrows, ncols);
    reduce_c_kernel<<<rcGrid, blk>>>(ncols);
    // iter 1 (row)
    rowsum_h<<<rsGrid, blk>>>(nrows, ncols);

    // iters 2..7: three (col, row) pairs on staged fp16
    for (int p = 0; p < 3; ++p) {
        colsum_h<<<csGrid, blk>>>(nrows, ncols);
        reduce_c_kernel<<<rcGrid, blk>>>(ncols);
        rowsum_h<<<rsGrid, blk>>>(nrows, ncols);
    }
    // iter 8 (col)
    colsum_h<<<csGrid, blk>>>(nrows, ncols);
    reduce_c_kernel<<<rcGrid, blk>>>(ncols);
    // iter 9 (row) fused with output materialization
    rowsum_final<<<rsGrid, blk>>>(s, nrows, ncols, out);
}

// round 10
// speedup vs baseline: 1.1961x; 1.1961x over previous
#include <cuda_runtime.h>
#include <cuda_fp16.h>

// Sinkhorn rank-one factorization: out = (s0+eps)*r_i*c_j inside the
// [nrows, ncols] block. All 10 matvecs AND the final output use an fp16
// staged copy of (s0+eps), zero-padded past ncols within 16B granules.
// fp16 RN error <= 2^-11 (4.9e-4) deterministic, under the 1e-3 gate.

#define BB 64
#define NN 1024
#define MM 1024
#define SPLIT 32
#define EPSV 1e-4f

__device__ __align__(16) __half g_sh[(size_t)BB * NN * MM];   // 128 MB (bss)
__device__ __align__(16) float  g_r[BB * NN];
__device__ __align__(16) float  g_c[BB * MM];
__device__ __align__(16) float  g_part[(size_t)BB * SPLIT * MM];

// ---------------------------------------------------------------------------
// Fused: stage (s+eps)->fp16 (zero past ncols) AND iteration-0 column-sum
// partials (implicit r = 1). Thread t owns 4 consecutive columns.
// ---------------------------------------------------------------------------
__global__ __launch_bounds__(256) void stage_colsum0(
        const float* __restrict__ s,
        const int* __restrict__ nrows,
        const int* __restrict__ ncols) {
    int b = blockIdx.y;
    int t = threadIdx.x;                    // 256 threads * 4 cols = 1024
    int nr = nrows[b], nc = ncols[b];
    int chunk = (nr + SPLIT - 1) / SPLIT;
    int i0 = blockIdx.x * chunk;
    int i1 = min(i0 + chunk, nr);
    int j = t * 4;
    bool m0 = j < nc, m1 = j + 1 < nc, m2 = j + 2 < nc, m3 = j + 3 < nc;

    float4 acc = make_float4(0.f, 0.f, 0.f, 0.f);
    const float4* __restrict__ sp =
        (const float4*)(s + ((size_t)b * NN + i0) * MM) + t;
    __half2* __restrict__ hp =
        (__half2*)(g_sh + ((size_t)b * NN + i0) * MM) + t * 2;

    for (int i = i0; i < i1; i++) {
        float x0 = 0.f, x1 = 0.f, x2 = 0.f, x3 = 0.f;
        if (m0) {
            float4 v = *sp;
            x0 = v.x + EPSV;
            x1 = m1 ? v.y + EPSV : 0.f;
            x2 = m2 ? v.z + EPSV : 0.f;
            x3 = m3 ? v.w + EPSV : 0.f;
        }
        hp[0] = __floats2half2_rn(x0, x1);
        hp[1] = __floats2half2_rn(x2, x3);
        acc.x += x0; acc.y += x1; acc.z += x2; acc.w += x3;
        sp += MM / 4;
        hp += MM / 2;
    }
    ((float4*)(g_part + ((size_t)b * SPLIT + blockIdx.x) * MM))[t] = acc;
}

// ---------------------------------------------------------------------------
// c[b,j] = 1 / sum_k part[b,k,j]  (j < ncols; else 1.0)
// ---------------------------------------------------------------------------
__global__ __launch_bounds__(256) void reduce_c_kernel(
        const int* __restrict__ ncols) {
    int b = blockIdx.y;
    int j = blockIdx.x * 256 + threadIdx.x;
    float sum = 0.f;
    #pragma unroll
    for (int k = 0; k < SPLIT; k++)
        sum += g_part[((size_t)b * SPLIT + k) * MM + j];
    g_c[b * MM + j] = (j < ncols[b]) ? (1.0f / sum) : 1.0f;
}

// ---------------------------------------------------------------------------
// Column-sum partials on staged fp16 weighted by r (R7-proven body).
// ---------------------------------------------------------------------------
__global__ __launch_bounds__(256) void colsum_h(
        const int* __restrict__ nrows,
        const int* __restrict__ ncols) {
    int b = blockIdx.y;
    int t = threadIdx.x;
    int nr = nrows[b], nc = ncols[b];
    int chunk = (nr + SPLIT - 1) / SPLIT;
    int i0 = blockIdx.x * chunk;
    int i1 = min(i0 + chunk, nr);

    float4 acc = make_float4(0.f, 0.f, 0.f, 0.f);
    if (t * 4 < nc) {
        const float2* __restrict__ hp =
            (const float2*)(g_sh + ((size_t)b * NN + i0) * MM) + t;
        const float* __restrict__ rp = g_r + b * NN;
        #pragma unroll 4
        for (int i = i0; i < i1; i++) {
            float2 raw = hp[(size_t)(i - i0) * (MM / 4)];
            __half2 h0 = *(__half2*)&raw.x;
            __half2 h1 = *(__half2*)&raw.y;
            float2 a = __half22float2(h0);
            float2 d = __half22float2(h1);
            float r = rp[i];
            acc.x += a.x * r; acc.y += a.y * r;
            acc.z += d.x * r; acc.w += d.y * r;
        }
    }
    ((float4*)(g_part + ((size_t)b * SPLIT + blockIdx.x) * MM))[t] = acc;
}

// ---------------------------------------------------------------------------
// r[b,i] = 1 / sum_j staged * c.  Warp per valid row (R7-proven body).
// ---------------------------------------------------------------------------
__global__ __launch_bounds__(256) void rowsum_h(
        const int* __restrict__ nrows,
        const int* __restrict__ ncols) {
    int b = blockIdx.y;
    int lane = threadIdx.x & 31, w = threadIdx.x >> 5;
    int i = blockIdx.x * 8 + w;
    if (i >= nrows[b]) return;
    int nc = ncols[b];

    const float2* __restrict__ hp =
        (const float2*)(g_sh + ((size_t)b * NN + i) * MM);
    const float4* __restrict__ cp = (const float4*)(g_c + (size_t)b * MM);
    float acc = 0.f;
    int ng = (nc + 3) >> 2;
    #pragma unroll 4
    for (int j4 = lane; j4 < ng; j4 += 32) {
        float2 raw = hp[j4];
        __half2 h0 = *(__half2*)&raw.x;
        __half2 h1 = *(__half2*)&raw.y;
        float2 a = __half22float2(h0);
        float2 d = __half22float2(h1);
        float4 c = cp[j4];
        acc += a.x * c.x + a.y * c.y + d.x * c.z + d.y * c.w;
    }
    #pragma unroll
    for (int o = 16; o; o >>= 1) acc += __shfl_xor_sync(0xffffffffu, acc, o);
    if (lane == 0) g_r[b * NN + i] = 1.0f / acc;
}

// ---------------------------------------------------------------------------
// Fused iter-9 rowsum + output, fp16 source. Warp per row. Each lane caches
// its 4 granules (8 halves each) in registers: one global read of the row.
// Granule zero-padding => no column masks anywhere; invalid rows write 0.
// ---------------------------------------------------------------------------
__global__ __launch_bounds__(256) void rowsum_final_h(
        const int* __restrict__ nrows,
        const int* __restrict__ ncols,
        float* __restrict__ out) {
    int b = blockIdx.y;
    int lane = threadIdx.x & 31, w = threadIdx.x >> 5;
    int i = blockIdx.x * 8 + w;
    int nr = nrows[b], nc = ncols[b];
    float4* __restrict__ op = (float4*)(out + ((size_t)b * NN + i) * MM);

    if (i >= nr) {
        float4 z = make_float4(0.f, 0.f, 0.f, 0.f);
        #pragma unroll
        for (int k = lane; k < MM / 4; k += 32) op[k] = z;
        return;
    }

    const uint4* __restrict__ hp =
        (const uint4*)(g_sh + ((size_t)b * NN + i) * MM);
    const float4* __restrict__ cp = (const float4*)(g_c + (size_t)b * MM);
    int ng8 = (nc + 7) >> 3;          // valid 8-half granules

    uint4 hreg[4];
    float acc = 0.f;
    #pragma unroll
    for (int q = 0; q < 4; q++) {
        int g = lane + 32 * q;
        uint4 raw = make_uint4(0u, 0u, 0u, 0u);
        if (g < ng8) raw = hp[g];
        hreg[q] = raw;
        float4 c0 = cp[2 * g], c1 = cp[2 * g + 1];
        float2 a0 = __half22float2(*(__half2*)&raw.x);
        float2 a1 = __half22float2(*(__half2*)&raw.y);
        float2 a2 = __half22float2(*(__half2*)&raw.z);
        float2 a3 = __half22float2(*(__half2*)&raw.w);
        acc += a0.x * c0.x + a0.y * c0.y + a1.x * c0.z + a1.y * c0.w
             + a2.x * c1.x + a2.y * c1.y + a3.x * c1.z + a3.y * c1.w;
    }
    #pragma unroll
    for (int o = 16; o; o >>= 1) acc += __shfl_xor_sync(0xffffffffu, acc, o);
    float r = 1.0f / acc;

    #pragma unroll
    for (int q = 0; q < 4; q++) {
        int g = lane + 32 * q;
        uint4 raw = hreg[q];
        float4 c0 = cp[2 * g], c1 = cp[2 * g + 1];
        float2 a0 = __half22float2(*(__half2*)&raw.x);
        float2 a1 = __half22float2(*(__half2*)&raw.y);
        float2 a2 = __half22float2(*(__half2*)&raw.z);
        float2 a3 = __half22float2(*(__half2*)&raw.w);
        float4 o0, o1;
        o0.x = a0.x * r * c0.x;  o0.y = a0.y * r * c0.y;
        o0.z = a1.x * r * c0.z;  o0.w = a1.y * r * c0.w;
        o1.x = a2.x * r * c1.x;  o1.y = a2.y * r * c1.y;
        o1.z = a3.x * r * c1.z;  o1.w = a3.y * r * c1.w;
        op[2 * g] = o0;
        op[2 * g + 1] = o1;
    }
}

// ---------------------------------------------------------------------------
extern "C" void kernel_launch(void* const* d_in, const int* in_sizes, int n_in,
                              void* d_out, int out_size) {
    const float* s     = (const float*)d_in[0];
    const int*   nrows = (const int*)d_in[1];
    const int*   ncols = (const int*)d_in[2];
    float*       out   = (float*)d_out;

    dim3 csGrid(SPLIT, BB),    blk(256);
    dim3 rcGrid(MM / 256, BB);
    dim3 rsGrid(NN / 8, BB);

    // iter 0 (col): fused stage + colsum with implicit r = 1
    stage_colsum0<<<csGrid, blk>>>(s, nrows, ncols);
    reduce_c_kernel<<<rcGrid, blk>>>(ncols);
    // iter 1 (row)
    rowsum_h<<<rsGrid, blk>>>(nrows, ncols);

    // iters 2..7: three (col, row) pairs on staged fp16
    for (int p = 0; p < 3; ++p) {
        colsum_h<<<csGrid, blk>>>(nrows, ncols);
        reduce_c_kernel<<<rcGrid, blk>>>(ncols);
        rowsum_h<<<rsGrid, blk>>>(nrows, ncols);
    }
    // iter 8 (col)
    colsum_h<<<csGrid, blk>>>(nrows, ncols);
    reduce_c_kernel<<<rcGrid, blk>>>(ncols);
    // iter 9 (row) fused with output materialization, fp16 source
    rowsum_final_h<<<rsGrid, blk>>>(nrows, ncols, out);
}

// round 11
// speedup vs baseline: 1.2695x; 1.0614x over previous
#include <cuda_runtime.h>
#include <cuda_fp16.h>

// Sinkhorn rank-one factorization: out = (s0+eps)*r_i*c_j inside the
// [nrows, ncols] block. fp16 staged copy of (s0+eps), zero-padded past
// ncols. Row-normalize and the NEXT column-sum are FUSED into one pass:
// a warp computes r_i for its row, then accumulates r_i*row into 32
// register-resident column partials (lane owns fixed columns).

#define BB 64
#define NN 1024
#define MM 1024
#define SSPLIT 32            // row chunks for stage kernel
#define RSPLIT 16            // row chunks for fused kernel
#define PSLOTS 32            // g_part slot stride per batch
#define EPSV 1e-4f

__device__ __align__(16) __half g_sh[(size_t)BB * NN * MM];   // 128 MB (bss)
__device__ __align__(16) float  g_c[BB * MM];
__device__ __align__(16) float  g_part[(size_t)BB * PSLOTS * MM];

// swizzled smem index for column c: g = c>>3, k = c&7 -> k*128 + g
#define SWZ(c) ((((c) & 7) << 7) | ((c) >> 3))

// ---------------------------------------------------------------------------
// Fused: stage (s+eps)->fp16 (zero past ncols) AND iteration-0 column-sum
// partials (implicit r = 1). Thread t owns 4 consecutive columns.
// ---------------------------------------------------------------------------
__global__ __launch_bounds__(256) void stage_colsum0(
        const float* __restrict__ s,
        const int* __restrict__ nrows,
        const int* __restrict__ ncols) {
    int b = blockIdx.y;
    int t = threadIdx.x;
    int nr = nrows[b], nc = ncols[b];
    int chunk = (nr + SSPLIT - 1) / SSPLIT;
    int i0 = blockIdx.x * chunk;
    int i1 = min(i0 + chunk, nr);
    int j = t * 4;
    bool m0 = j < nc, m1 = j + 1 < nc, m2 = j + 2 < nc, m3 = j + 3 < nc;

    float4 acc = make_float4(0.f, 0.f, 0.f, 0.f);
    const float4* __restrict__ sp =
        (const float4*)(s + ((size_t)b * NN + i0) * MM) + t;
    __half2* __restrict__ hp =
        (__half2*)(g_sh + ((size_t)b * NN + i0) * MM) + t * 2;

    for (int i = i0; i < i1; i++) {
        float x0 = 0.f, x1 = 0.f, x2 = 0.f, x3 = 0.f;
        if (m0) {
            float4 v = *sp;
            x0 = v.x + EPSV;
            x1 = m1 ? v.y + EPSV : 0.f;
            x2 = m2 ? v.z + EPSV : 0.f;
            x3 = m3 ? v.w + EPSV : 0.f;
        }
        hp[0] = __floats2half2_rn(x0, x1);
        hp[1] = __floats2half2_rn(x2, x3);
        acc.x += x0; acc.y += x1; acc.z += x2; acc.w += x3;
        sp += MM / 4;
        hp += MM / 2;
    }
    ((float4*)(g_part + ((size_t)b * PSLOTS + blockIdx.x) * MM))[t] = acc;
}

// ---------------------------------------------------------------------------
// c[b,j] = 1 / sum_{k<ns} part[b,k,j]  (j < ncols; else 1.0)
// ---------------------------------------------------------------------------
__global__ __launch_bounds__(256) void reduce_c_kernel(
        const int* __restrict__ ncols, int ns) {
    int b = blockIdx.y;
    int j = blockIdx.x * 256 + threadIdx.x;
    float sum = 0.f;
    for (int k = 0; k < ns; k++)
        sum += g_part[((size_t)b * PSLOTS + k) * MM + j];
    g_c[b * MM + j] = (j < ncols[b]) ? (1.0f / sum) : 1.0f;
}

// ---------------------------------------------------------------------------
// FUSED row-normalize + next column-sum. Warp per row (round-robin over the
// block's chunk). Lane owns granules g = lane+32q (columns 8g..8g+7) and
// keeps 32 column partials in registers; c is read from swizzled smem
// (conflict-free); block combines 8 warp partials once via swizzled smem.
// ---------------------------------------------------------------------------
__global__ __launch_bounds__(256) void rowcol_fused(
        const int* __restrict__ nrows,
        const int* __restrict__ ncols) {
    __shared__ float c_s[MM];            // swizzled
    __shared__ float sacc[8][MM];        // swizzled, per-warp
    int b = blockIdx.y;
    int t = threadIdx.x;
    int lane = t & 31, w = t >> 5;
    int nr = nrows[b];
    int chunk = (nr + RSPLIT - 1) / RSPLIT;
    int i0 = blockIdx.x * chunk;
    int i1 = min(i0 + chunk, nr);

    {   // stage c into swizzled smem (once per block)
        float4 cv = ((const float4*)(g_c + (size_t)b * MM))[t];
        int col = t * 4;
        c_s[SWZ(col + 0)] = cv.x;
        c_s[SWZ(col + 1)] = cv.y;
        c_s[SWZ(col + 2)] = cv.z;
        c_s[SWZ(col + 3)] = cv.w;
    }
    float colacc[32];
    #pragma unroll
    for (int k = 0; k < 32; k++) colacc[k] = 0.f;
    __syncthreads();

    const uint4* __restrict__ hb = (const uint4*)(g_sh + (size_t)b * NN * MM);
    for (int i = i0 + w; i < i1; i += 8) {
        const uint4* hp = hb + (size_t)i * (MM / 8);
        uint4 raw[4];
        #pragma unroll
        for (int q = 0; q < 4; q++) raw[q] = hp[lane + 32 * q];

        float dot = 0.f;
        #pragma unroll
        for (int q = 0; q < 4; q++) {
            int g = lane + 32 * q;
            float2 a0 = __half22float2(*(__half2*)&raw[q].x);
            float2 a1 = __half22float2(*(__half2*)&raw[q].y);
            float2 a2 = __half22float2(*(__half2*)&raw[q].z);
            float2 a3 = __half22float2(*(__half2*)&raw[q].w);
            dot += a0.x * c_s[0 * 128 + g] + a0.y * c_s[1 * 128 + g]
                 + a1.x * c_s[2 * 128 + g] + a1.y * c_s[3 * 128 + g]
                 + a2.x * c_s[4 * 128 + g] + a2.y * c_s[5 * 128 + g]
                 + a3.x * c_s[6 * 128 + g] + a3.y * c_s[7 * 128 + g];
        }
        #pragma unroll
        for (int o = 16; o; o >>= 1)
            dot += __shfl_xor_sync(0xffffffffu, dot, o);
        float r = 1.0f / dot;

        #pragma unroll
        for (int q = 0; q < 4; q++) {
            float2 a0 = __half22float2(*(__half2*)&raw[q].x);
            float2 a1 = __half22float2(*(__half2*)&raw[q].y);
            float2 a2 = __half22float2(*(__half2*)&raw[q].z);
            float2 a3 = __half22float2(*(__half2*)&raw[q].w);
            colacc[q * 8 + 0] += r * a0.x;
            colacc[q * 8 + 1] += r * a0.y;
            colacc[q * 8 + 2] += r * a1.x;
            colacc[q * 8 + 3] += r * a1.y;
            colacc[q * 8 + 4] += r * a2.x;
            colacc[q * 8 + 5] += r * a2.y;
            colacc[q * 8 + 6] += r * a3.x;
            colacc[q * 8 + 7] += r * a3.y;
        }
    }

    // spill warp partials (conflict-free swizzled addresses)
    #pragma unroll
    for (int q = 0; q < 4; q++) {
        int g = lane + 32 * q;
        #pragma unroll
        for (int k = 0; k < 8; k++)
            sacc[w][k * 128 + g] = colacc[q * 8 + k];
    }
    __syncthreads();

    // block reduce: thread t -> columns 4t..4t+3, one float4 partial write
    int col = t * 4;
    float4 o;
    float* po = &o.x;
    #pragma unroll
    for (int m = 0; m < 4; m++) {
        int idx = SWZ(col + m);
        float s = 0.f;
        #pragma unroll
        for (int ww = 0; ww < 8; ww++) s += sacc[ww][idx];
        po[m] = s;
    }
    ((float4*)(g_part + ((size_t)b * PSLOTS + blockIdx.x) * MM))[t] = o;
}

// ---------------------------------------------------------------------------
// Fused iter-9 rowsum + output, fp16 source (R10-proven). Warp per row.
// ---------------------------------------------------------------------------
__global__ __launch_bounds__(256) void rowsum_final_h(
        const int* __restrict__ nrows,
        const int* __restrict__ ncols,
        float* __restrict__ out) {
    int b = blockIdx.y;
    int lane = threadIdx.x & 31, w = threadIdx.x >> 5;
    int i = blockIdx.x * 8 + w;
    int nr = nrows[b], nc = ncols[b];
    float4* __restrict__ op = (float4*)(out + ((size_t)b * NN + i) * MM);

    if (i >= nr) {
        float4 z = make_float4(0.f, 0.f, 0.f, 0.f);
        #pragma unroll
        for (int k = lane; k < MM / 4; k += 32) op[k] = z;
        return;
    }

    const uint4* __restrict__ hp =
        (const uint4*)(g_sh + ((size_t)b * NN + i) * MM);
    const float4* __restrict__ cp = (const float4*)(g_c + (size_t)b * MM);
    int ng8 = (nc + 7) >> 3;

    uint4 hreg[4];
    float acc = 0.f;
    #pragma unroll
    for (int q = 0; q < 4; q++) {
        int g = lane + 32 * q;
        uint4 raw = make_uint4(0u, 0u, 0u, 0u);
        if (g < ng8) raw = hp[g];
        hreg[q] = raw;
        float4 c0 = cp[2 * g], c1 = cp[2 * g + 1];
        float2 a0 = __half22float2(*(__half2*)&raw.x);
        float2 a1 = __half22float2(*(__half2*)&raw.y);
        float2 a2 = __half22float2(*(__half2*)&raw.z);
        float2 a3 = __half22float2(*(__half2*)&raw.w);
        acc += a0.x * c0.x + a0.y * c0.y + a1.x * c0.z + a1.y * c0.w
             + a2.x * c1.x + a2.y * c1.y + a3.x * c1.z + a3.y * c1.w;
    }
    #pragma unroll
    for (int o = 16; o; o >>= 1) acc += __shfl_xor_sync(0xffffffffu, acc, o);
    float r = 1.0f / acc;

    #pragma unroll
    for (int q = 0; q < 4; q++) {
        int g = lane + 32 * q;
        uint4 raw = hreg[q];
        float4 c0 = cp[2 * g], c1 = cp[2 * g + 1];
        float2 a0 = __half22float2(*(__half2*)&raw.x);
        float2 a1 = __half22float2(*(__half2*)&raw.y);
        float2 a2 = __half22float2(*(__half2*)&raw.z);
        float2 a3 = __half22float2(*(__half2*)&raw.w);
        float4 o0, o1;
        o0.x = a0.x * r * c0.x;  o0.y = a0.y * r * c0.y;
        o0.z = a1.x * r * c0.z;  o0.w = a1.y * r * c0.w;
        o1.x = a2.x * r * c1.x;  o1.y = a2.y * r * c1.y;
        o1.z = a3.x * r * c1.z;  o1.w = a3.y * r * c1.w;
        op[2 * g] = o0;
        op[2 * g + 1] = o1;
    }
}

// ---------------------------------------------------------------------------
extern "C" void kernel_launch(void* const* d_in, const int* in_sizes, int n_in,
                              void* d_out, int out_size) {
    const float* s     = (const float*)d_in[0];
    const int*   nrows = (const int*)d_in[1];
    const int*   ncols = (const int*)d_in[2];
    float*       out   = (float*)d_out;

    dim3 stGrid(SSPLIT, BB),   blk(256);
    dim3 rcGrid(MM / 256, BB);
    dim3 fuGrid(RSPLIT, BB);
    dim3 rsGrid(NN / 8, BB);

    // iter 0 (col): fused stage + colsum with implicit r = 1
    stage_colsum0<<<stGrid, blk>>>(s, nrows, ncols);
    reduce_c_kernel<<<rcGrid, blk>>>(ncols, SSPLIT);

    // iters 1..8: four fused (row-normalize + next column-sum) passes
    for (int p = 0; p < 4; ++p) {
        rowcol_fused<<<fuGrid, blk>>>(nrows, ncols);
        reduce_c_kernel<<<rcGrid, blk>>>(ncols, RSPLIT);
    }

    // iter 9 (row) fused with output materialization, fp16 source
    rowsum_final_h<<<rsGrid, blk>>>(nrows, ncols, out);
}